// round 1
// baseline (speedup 1.0000x reference)
#include <cuda_runtime.h>
#include <cstdint>

#define N_NODES 50000
#define N_EDGES 400000
#define D_IN    1024
#define D_HID   512
#define D_LAT   256

// Scratch (allocation-free rule: __device__ globals)
__device__ float g_s1[(size_t)N_NODES * D_HID];   // x @ W1
__device__ float g_h [(size_t)N_NODES * D_HID];   // agg1 -> relu'd h (in place)
__device__ float g_s2[(size_t)N_NODES * D_LAT];   // h @ W2

// ---------------------------------------------------------------------------
// helpers
// ---------------------------------------------------------------------------
__device__ __forceinline__ uint32_t f2tf32(float x) {
    uint32_t y;
    asm("cvt.rna.tf32.f32 %0, %1;" : "=r"(y) : "f"(x));
    return y;
}

__device__ __forceinline__ void mma_tf32(float c[4], const uint32_t a[4], const uint32_t b[2]) {
    asm volatile(
        "mma.sync.aligned.m16n8k8.row.col.f32.tf32.tf32.f32 "
        "{%0,%1,%2,%3}, {%4,%5,%6,%7}, {%8,%9}, {%0,%1,%2,%3};"
        : "+f"(c[0]), "+f"(c[1]), "+f"(c[2]), "+f"(c[3])
        : "r"(a[0]), "r"(a[1]), "r"(a[2]), "r"(a[3]), "r"(b[0]), "r"(b[1]));
}

// ---------------------------------------------------------------------------
// TF32 tensor-core GEMM: C[M,N] = A[M,K] @ B[K,N]   (A,B,C row-major fp32)
// Tile 128x128x16, 256 threads (8 warps, warp tile 64x32)
// ---------------------------------------------------------------------------
#define BM 128
#define BN 128
#define BKK 16

__global__ __launch_bounds__(256)
void gemm_tf32(const float* __restrict__ A, const float* __restrict__ B,
               float* __restrict__ C, int M, int N, int K) {
    __shared__ uint32_t As[BM][BKK + 4];   // stride 20 -> conflict-free frag loads
    __shared__ uint32_t Bs[BKK][BN + 8];   // stride 136 (== 8 mod 32) -> conflict-free

    const int tid  = threadIdx.x;
    const int lane = tid & 31;
    const int wid  = tid >> 5;
    const int warp_m = wid & 1;     // 2 warps along M
    const int warp_n = wid >> 1;    // 4 warps along N
    const int qr = lane >> 2;       // 0..7
    const int qc = lane & 3;        // 0..3
    const int brow = blockIdx.x * BM;
    const int bcol = blockIdx.y * BN;

    float acc[4][4][4];
    #pragma unroll
    for (int i = 0; i < 4; i++)
        #pragma unroll
        for (int j = 0; j < 4; j++)
            #pragma unroll
            for (int k = 0; k < 4; k++) acc[i][j][k] = 0.f;

    for (int kb = 0; kb < K; kb += BKK) {
        // A tile: BMxBKK = 512 float4, 2 per thread
        #pragma unroll
        for (int f = tid; f < (BM * BKK) / 4; f += 256) {
            int r  = f >> 2;            // 4 float4 per row
            int c4 = (f & 3) << 2;
            int gr = brow + r;
            float4 v = make_float4(0.f, 0.f, 0.f, 0.f);
            if (gr < M) v = *(const float4*)(A + (size_t)gr * K + kb + c4);
            As[r][c4 + 0] = f2tf32(v.x);
            As[r][c4 + 1] = f2tf32(v.y);
            As[r][c4 + 2] = f2tf32(v.z);
            As[r][c4 + 3] = f2tf32(v.w);
        }
        // B tile: BKKxBN = 512 float4, 2 per thread (K,N always divisible)
        #pragma unroll
        for (int f = tid; f < (BKK * BN) / 4; f += 256) {
            int r  = f >> 5;            // 32 float4 per row
            int c4 = (f & 31) << 2;
            float4 v = *(const float4*)(B + (size_t)(kb + r) * N + bcol + c4);
            Bs[r][c4 + 0] = f2tf32(v.x);
            Bs[r][c4 + 1] = f2tf32(v.y);
            Bs[r][c4 + 2] = f2tf32(v.z);
            Bs[r][c4 + 3] = f2tf32(v.w);
        }
        __syncthreads();

        #pragma unroll
        for (int ks = 0; ks < BKK; ks += 8) {
            uint32_t af[4][4], bf[4][2];
            #pragma unroll
            for (int mt = 0; mt < 4; mt++) {
                int r0 = warp_m * 64 + mt * 16 + qr;
                af[mt][0] = As[r0    ][ks + qc];
                af[mt][1] = As[r0 + 8][ks + qc];
                af[mt][2] = As[r0    ][ks + qc + 4];
                af[mt][3] = As[r0 + 8][ks + qc + 4];
            }
            #pragma unroll
            for (int nt = 0; nt < 4; nt++) {
                int c0 = warp_n * 32 + nt * 8 + qr;
                bf[nt][0] = Bs[ks + qc    ][c0];
                bf[nt][1] = Bs[ks + qc + 4][c0];
            }
            #pragma unroll
            for (int mt = 0; mt < 4; mt++)
                #pragma unroll
                for (int nt = 0; nt < 4; nt++)
                    mma_tf32(acc[mt][nt], af[mt], bf[nt]);
        }
        __syncthreads();
    }

    // epilogue
    #pragma unroll
    for (int mt = 0; mt < 4; mt++) {
        int r = brow + warp_m * 64 + mt * 16 + qr;
        #pragma unroll
        for (int nt = 0; nt < 4; nt++) {
            int c = bcol + warp_n * 32 + nt * 8 + qc * 2;
            if (r < M) {
                C[(size_t)r * N + c]     = acc[mt][nt][0];
                C[(size_t)r * N + c + 1] = acc[mt][nt][1];
            }
            if (r + 8 < M) {
                C[(size_t)(r + 8) * N + c]     = acc[mt][nt][2];
                C[(size_t)(r + 8) * N + c + 1] = acc[mt][nt][3];
            }
        }
    }
}

// ---------------------------------------------------------------------------
// Scatter-add: out[dst] += S[src] * w   via vector RED atomics (L2-resident)
// ---------------------------------------------------------------------------
template<int D>
__global__ __launch_bounds__(256)
void scatter_add(const float* __restrict__ S, const int* __restrict__ ei,
                 const float* __restrict__ ew, float* __restrict__ out) {
    constexpr int TPE = D / 4;        // threads per edge (float4 each)
    constexpr int EPB = 256 / TPE;    // edges per block
    const int e = blockIdx.x * EPB + threadIdx.x / TPE;
    if (e >= N_EDGES) return;
    const int j = threadIdx.x % TPE;
    const int src = ei[e];
    const int dst = ei[N_EDGES + e];
    const float w = ew[e];
    float4 v = ((const float4*)(S + (size_t)src * D))[j];
    v.x *= w; v.y *= w; v.z *= w; v.w *= w;
    float* op = out + (size_t)dst * D + j * 4;
    asm volatile("red.global.add.v4.f32 [%0], {%1,%2,%3,%4};"
                 :: "l"(op), "f"(v.x), "f"(v.y), "f"(v.z), "f"(v.w) : "memory");
}

// ---------------------------------------------------------------------------
// elementwise
// ---------------------------------------------------------------------------
__global__ void zero_f4(float4* __restrict__ p, int n4) {
    int i = blockIdx.x * blockDim.x + threadIdx.x;
    int stride = gridDim.x * blockDim.x;
    float4 z = make_float4(0.f, 0.f, 0.f, 0.f);
    for (; i < n4; i += stride) p[i] = z;
}

template<int D>
__global__ void bias_relu(float* __restrict__ p, const float* __restrict__ b, int n4) {
    int i = blockIdx.x * blockDim.x + threadIdx.x;
    int stride = gridDim.x * blockDim.x;
    for (; i < n4; i += stride) {
        float4 v = ((float4*)p)[i];
        float4 bb = ((const float4*)b)[i % (D / 4)];
        v.x = fmaxf(v.x + bb.x, 0.f);
        v.y = fmaxf(v.y + bb.y, 0.f);
        v.z = fmaxf(v.z + bb.z, 0.f);
        v.w = fmaxf(v.w + bb.w, 0.f);
        ((float4*)p)[i] = v;
    }
}

// ---------------------------------------------------------------------------
// launch
// ---------------------------------------------------------------------------
extern "C" void kernel_launch(void* const* d_in, const int* in_sizes, int n_in,
                              void* d_out, int out_size) {
    const float* x  = (const float*)d_in[0];
    const int*   ei = (const int*)  d_in[1];
    const float* ew = (const float*)d_in[2];
    const float* W1 = (const float*)d_in[3];
    const float* b1 = (const float*)d_in[4];
    const float* W2 = (const float*)d_in[5];
    const float* b2 = (const float*)d_in[6];
    float* out = (float*)d_out;

    float *s1, *h, *s2;
    cudaGetSymbolAddress((void**)&s1, g_s1);
    cudaGetSymbolAddress((void**)&h,  g_h);
    cudaGetSymbolAddress((void**)&s2, g_s2);

    const int mblocks = (N_NODES + BM - 1) / BM;   // 391

    // Layer 1
    dim3 g1(mblocks, D_HID / BN);                  // (391, 4)
    gemm_tf32<<<g1, 256>>>(x, W1, s1, N_NODES, D_HID, D_IN);
    zero_f4<<<4096, 256>>>((float4*)h, N_NODES * D_HID / 4);
    scatter_add<D_HID><<<N_EDGES / (256 / (D_HID / 4)), 256>>>(s1, ei, ew, h);
    bias_relu<D_HID><<<4096, 256>>>(h, b1, N_NODES * D_HID / 4);

    // Layer 2
    dim3 g2(mblocks, D_LAT / BN);                  // (391, 2)
    gemm_tf32<<<g2, 256>>>(h, W2, s2, N_NODES, D_LAT, D_HID);
    zero_f4<<<4096, 256>>>((float4*)out, N_NODES * D_LAT / 4);
    scatter_add<D_LAT><<<N_EDGES / (256 / (D_LAT / 4)), 256>>>(s2, ei, ew, out);
    bias_relu<D_LAT><<<4096, 256>>>(out, b2, N_NODES * D_LAT / 4);
}

// round 2
// speedup vs baseline: 1.1413x; 1.1413x over previous
#include <cuda_runtime.h>
#include <cstdint>

#define N_NODES 50000
#define N_EDGES 400000
#define D_IN    1024
#define D_HID   512
#define D_LAT   256

// Scratch (allocation-free rule: __device__ globals)
__device__ float g_s1[(size_t)N_NODES * D_HID];   // x @ W1
__device__ float g_h [(size_t)N_NODES * D_HID];   // agg1 (raw, relu+bias fused into GEMM2 A-load)
__device__ float g_s2[(size_t)N_NODES * D_LAT];   // relu(h+b1) @ W2

// ---------------------------------------------------------------------------
// helpers
// ---------------------------------------------------------------------------
__device__ __forceinline__ uint32_t f2tf32(float x) {
    uint32_t y;
    asm("cvt.rna.tf32.f32 %0, %1;" : "=r"(y) : "f"(x));
    return y;
}

__device__ __forceinline__ void mma_tf32(float c[4], const uint32_t a[4], const uint32_t b[2]) {
    asm volatile(
        "mma.sync.aligned.m16n8k8.row.col.f32.tf32.tf32.f32 "
        "{%0,%1,%2,%3}, {%4,%5,%6,%7}, {%8,%9}, {%0,%1,%2,%3};"
        : "+f"(c[0]), "+f"(c[1]), "+f"(c[2]), "+f"(c[3])
        : "r"(a[0]), "r"(a[1]), "r"(a[2]), "r"(a[3]), "r"(b[0]), "r"(b[1]));
}

// ---------------------------------------------------------------------------
// TF32 tensor-core GEMM, cp.async double-buffered: C = A[M,K] @ B[K,N]
// Tile 128x128x32, 256 threads (8 warps, warp tile 64x32).
// FUSED: A element -> relu(A + bias[k]) on the smem->fragment path
// (used for layer 2, where A is the raw aggregation and bias = b1).
// ---------------------------------------------------------------------------
#define BM 128
#define BN 128
#define BK 32

template<bool FUSED>
__global__ __launch_bounds__(256)
void gemm_tf32(const float* __restrict__ A, const float* __restrict__ B,
               const float* __restrict__ bias, float* __restrict__ C,
               int M, int N, int K) {
    __shared__ float As[2][BM][BK + 4];   // +16B pad
    __shared__ float Bs[2][BK][BN + 8];   // +32B pad

    const int tid  = threadIdx.x;
    const int lane = tid & 31;
    const int wid  = tid >> 5;
    const int warp_m = wid & 1;     // 2 warps along M
    const int warp_n = wid >> 1;    // 4 warps along N
    const int qr = lane >> 2;       // 0..7
    const int qc = lane & 3;        // 0..3
    const int brow = blockIdx.x * BM;
    const int bcol = blockIdx.y * BN;

    float acc[4][4][4];
    #pragma unroll
    for (int i = 0; i < 4; i++)
        #pragma unroll
        for (int j = 0; j < 4; j++)
            #pragma unroll
            for (int k = 0; k < 4; k++) acc[i][j][k] = 0.f;

    // async tile loaders --------------------------------------------------
    auto load_tiles = [&](int kb, int buf) {
        // A tile: BMxBK = 1024 float4, 4 per thread
        #pragma unroll
        for (int i = 0; i < 4; i++) {
            int f  = tid + i * 256;
            int r  = f >> 3;             // 8 float4 per row
            int c4 = (f & 7) << 2;
            int gr = brow + r;
            uint32_t dst = (uint32_t)__cvta_generic_to_shared(&As[buf][r][c4]);
            const float* src = A + (size_t)gr * K + kb + c4;
            int sz = (gr < M) ? 16 : 0;  // zero-fill OOB rows
            asm volatile("cp.async.ca.shared.global [%0], [%1], 16, %2;\n"
                         :: "r"(dst), "l"(src), "r"(sz));
        }
        // B tile: BKxBN = 1024 float4, 4 per thread (always in-bounds)
        #pragma unroll
        for (int i = 0; i < 4; i++) {
            int f  = tid + i * 256;
            int r  = f >> 5;             // 32 float4 per row
            int c4 = (f & 31) << 2;
            uint32_t dst = (uint32_t)__cvta_generic_to_shared(&Bs[buf][r][c4]);
            const float* src = B + (size_t)(kb + r) * N + bcol + c4;
            asm volatile("cp.async.ca.shared.global [%0], [%1], 16;\n"
                         :: "r"(dst), "l"(src));
        }
        asm volatile("cp.async.commit_group;\n");
    };

    const int nk = K / BK;
    load_tiles(0, 0);

    for (int kt = 0; kt < nk; kt++) {
        const int buf = kt & 1;
        if (kt + 1 < nk) {
            load_tiles((kt + 1) * BK, buf ^ 1);
            asm volatile("cp.async.wait_group 1;\n");
        } else {
            asm volatile("cp.async.wait_group 0;\n");
        }
        __syncthreads();

        #pragma unroll
        for (int ks = 0; ks < BK; ks += 8) {
            float blo = 0.f, bhi = 0.f;
            if (FUSED) {
                blo = __ldg(bias + kt * BK + ks + qc);
                bhi = __ldg(bias + kt * BK + ks + qc + 4);
            }
            uint32_t af[4][4], bf[4][2];
            #pragma unroll
            for (int mt = 0; mt < 4; mt++) {
                int r0 = warp_m * 64 + mt * 16 + qr;
                float a0 = As[buf][r0    ][ks + qc];
                float a1 = As[buf][r0 + 8][ks + qc];
                float a2 = As[buf][r0    ][ks + qc + 4];
                float a3 = As[buf][r0 + 8][ks + qc + 4];
                if (FUSED) {
                    a0 = fmaxf(a0 + blo, 0.f);
                    a1 = fmaxf(a1 + blo, 0.f);
                    a2 = fmaxf(a2 + bhi, 0.f);
                    a3 = fmaxf(a3 + bhi, 0.f);
                }
                af[mt][0] = f2tf32(a0);
                af[mt][1] = f2tf32(a1);
                af[mt][2] = f2tf32(a2);
                af[mt][3] = f2tf32(a3);
            }
            #pragma unroll
            for (int nt = 0; nt < 4; nt++) {
                int c0 = warp_n * 32 + nt * 8 + qr;
                bf[nt][0] = f2tf32(Bs[buf][ks + qc    ][c0]);
                bf[nt][1] = f2tf32(Bs[buf][ks + qc + 4][c0]);
            }
            #pragma unroll
            for (int mt = 0; mt < 4; mt++)
                #pragma unroll
                for (int nt = 0; nt < 4; nt++)
                    mma_tf32(acc[mt][nt], af[mt], bf[nt]);
        }
        __syncthreads();
    }

    // epilogue
    #pragma unroll
    for (int mt = 0; mt < 4; mt++) {
        int r = brow + warp_m * 64 + mt * 16 + qr;
        #pragma unroll
        for (int nt = 0; nt < 4; nt++) {
            int c = bcol + warp_n * 32 + nt * 8 + qc * 2;
            if (r < M) {
                C[(size_t)r * N + c]     = acc[mt][nt][0];
                C[(size_t)r * N + c + 1] = acc[mt][nt][1];
            }
            if (r + 8 < M) {
                C[(size_t)(r + 8) * N + c]     = acc[mt][nt][2];
                C[(size_t)(r + 8) * N + c + 1] = acc[mt][nt][3];
            }
        }
    }
}

// ---------------------------------------------------------------------------
// Scatter-add: out[dst] += S[src] * w   via vector RED atomics (L2-resident)
// ---------------------------------------------------------------------------
template<int D>
__global__ __launch_bounds__(256)
void scatter_add(const float* __restrict__ S, const int* __restrict__ ei,
                 const float* __restrict__ ew, float* __restrict__ out) {
    constexpr int TPE = D / 4;        // threads per edge (float4 each)
    constexpr int EPB = 256 / TPE;    // edges per block
    const int e = blockIdx.x * EPB + threadIdx.x / TPE;
    if (e >= N_EDGES) return;
    const int j = threadIdx.x % TPE;
    const int src = ei[e];
    const int dst = ei[N_EDGES + e];
    const float w = ew[e];
    float4 v = ((const float4*)(S + (size_t)src * D))[j];
    v.x *= w; v.y *= w; v.z *= w; v.w *= w;
    float* op = out + (size_t)dst * D + j * 4;
    asm volatile("red.global.add.v4.f32 [%0], {%1,%2,%3,%4};"
                 :: "l"(op), "f"(v.x), "f"(v.y), "f"(v.z), "f"(v.w) : "memory");
}

// ---------------------------------------------------------------------------
// final bias + relu (layer-2 output only; layer-1's is fused into GEMM2)
// ---------------------------------------------------------------------------
template<int D>
__global__ void bias_relu(float* __restrict__ p, const float* __restrict__ b, int n4) {
    int i = blockIdx.x * blockDim.x + threadIdx.x;
    int stride = gridDim.x * blockDim.x;
    for (; i < n4; i += stride) {
        float4 v = ((float4*)p)[i];
        float4 bb = ((const float4*)b)[i % (D / 4)];
        v.x = fmaxf(v.x + bb.x, 0.f);
        v.y = fmaxf(v.y + bb.y, 0.f);
        v.z = fmaxf(v.z + bb.z, 0.f);
        v.w = fmaxf(v.w + bb.w, 0.f);
        ((float4*)p)[i] = v;
    }
}

// ---------------------------------------------------------------------------
// launch
// ---------------------------------------------------------------------------
extern "C" void kernel_launch(void* const* d_in, const int* in_sizes, int n_in,
                              void* d_out, int out_size) {
    const float* x  = (const float*)d_in[0];
    const int*   ei = (const int*)  d_in[1];
    const float* ew = (const float*)d_in[2];
    const float* W1 = (const float*)d_in[3];
    const float* b1 = (const float*)d_in[4];
    const float* W2 = (const float*)d_in[5];
    const float* b2 = (const float*)d_in[6];
    float* out = (float*)d_out;

    float *s1, *h, *s2;
    cudaGetSymbolAddress((void**)&s1, g_s1);
    cudaGetSymbolAddress((void**)&h,  g_h);
    cudaGetSymbolAddress((void**)&s2, g_s2);

    const int mblocks = (N_NODES + BM - 1) / BM;   // 391

    // Layer 1: s1 = x @ W1 ; h = scatter(s1)          (bias+relu deferred)
    dim3 g1(mblocks, D_HID / BN);                  // (391, 4)
    gemm_tf32<false><<<g1, 256>>>(x, W1, nullptr, s1, N_NODES, D_HID, D_IN);
    cudaMemsetAsync(h, 0, (size_t)N_NODES * D_HID * sizeof(float));
    scatter_add<D_HID><<<N_EDGES / (256 / (D_HID / 4)), 256>>>(s1, ei, ew, h);

    // Layer 2: s2 = relu(h + b1) @ W2 (fused) ; out = relu(scatter(s2) + b2)
    dim3 g2(mblocks, D_LAT / BN);                  // (391, 2)
    gemm_tf32<true><<<g2, 256>>>(h, W2, b1, s2, N_NODES, D_LAT, D_HID);
    cudaMemsetAsync(out, 0, (size_t)N_NODES * D_LAT * sizeof(float));
    scatter_add<D_LAT><<<N_EDGES / (256 / (D_LAT / 4)), 256>>>(s2, ei, ew, out);
    bias_relu<D_LAT><<<4096, 256>>>(out, b2, N_NODES * D_LAT / 4);
}

// round 4
// speedup vs baseline: 1.4016x; 1.2280x over previous
#include <cuda_runtime.h>
#include <cuda_fp16.h>
#include <cstdint>

#define N_NODES 50000
#define N_EDGES 400000
#define D_IN    1024
#define D_HID   512
#define D_LAT   256

// Scratch (allocation-free rule: __device__ globals)
__device__ float  g_s1 [(size_t)N_NODES * D_HID];   // x @ W1 (f32, scatter src)
__device__ float  g_h  [(size_t)N_NODES * D_HID];   // agg1 (f32, scatter dst)
__device__ float  g_s2 [(size_t)N_NODES * D_LAT];   // h @ W2 (f32, scatter src)
__device__ __half g_xh [(size_t)N_NODES * D_IN];    // x in fp16
__device__ __half g_hh [(size_t)N_NODES * D_HID];   // relu(h+b1) in fp16
__device__ __half g_w1t[(size_t)D_HID * D_IN];      // W1^T fp16 [N][K]
__device__ __half g_w2t[(size_t)D_LAT * D_HID];     // W2^T fp16 [N][K]

// ---------------------------------------------------------------------------
// fp16 mma.sync GEMM: C[M,N](f32) = A[M,K](f16) @ Bt[N,K](f16)^T
// CTA tile 128x256, BK=32, 3-stage cp.async, 256 thr (8 warps, warp 64x64).
// smem: per stage A 128x32 f16 (8KB) + B 256x32 f16 (16KB); rows of 16 words,
// XOR swizzle word' = word ^ (((row>>1)&3)<<2)  -> conflict-free LDS + 16B cp.
// ---------------------------------------------------------------------------
#define BM 128
#define BN 256
#define BK 32
#define STAGES 3
#define A_WORDS (BM * 16)                 // uint32 words per A stage
#define B_WORDS (BN * 16)
#define STAGE_WORDS (A_WORDS + B_WORDS)   // 6144 words = 24KB
#define SMEM_BYTES (STAGES * STAGE_WORDS * 4)

__device__ __forceinline__ void hmma(float c[4], const uint32_t a[4], const uint32_t b[2]) {
    asm volatile(
        "mma.sync.aligned.m16n8k16.row.col.f32.f16.f16.f32 "
        "{%0,%1,%2,%3}, {%4,%5,%6,%7}, {%8,%9}, {%0,%1,%2,%3};"
        : "+f"(c[0]), "+f"(c[1]), "+f"(c[2]), "+f"(c[3])
        : "r"(a[0]), "r"(a[1]), "r"(a[2]), "r"(a[3]), "r"(b[0]), "r"(b[1]));
}

__device__ __forceinline__ void cp16(uint32_t dst, const void* src, int sz) {
    asm volatile("cp.async.ca.shared.global [%0], [%1], 16, %2;\n"
                 :: "r"(dst), "l"(src), "r"(sz));
}
__device__ __forceinline__ void cp16u(uint32_t dst, const void* src) {
    asm volatile("cp.async.ca.shared.global [%0], [%1], 16;\n"
                 :: "r"(dst), "l"(src));
}

__global__ __launch_bounds__(256, 1)
void gemm_h(const __half* __restrict__ A, const __half* __restrict__ Bt,
            float* __restrict__ C, int M, int N, int K) {
    extern __shared__ uint32_t smem[];
    const uint32_t sbase = (uint32_t)__cvta_generic_to_shared(smem);

    const int tid  = threadIdx.x;
    const int lane = tid & 31;
    const int wid  = tid >> 5;
    const int warp_m = wid & 1;      // 2 warps along M
    const int warp_n = wid >> 1;     // 4 warps along N
    const int qr = lane >> 2;        // 0..7
    const int qc = lane & 3;         // 0..3
    const int brow = blockIdx.x * BM;
    const int bcol = blockIdx.y * BN;

    float acc[4][8][4];
    #pragma unroll
    for (int i = 0; i < 4; i++)
        #pragma unroll
        for (int j = 0; j < 8; j++)
            #pragma unroll
            for (int k = 0; k < 4; k++) acc[i][j][k] = 0.f;

    // async stage loader: A 128 rows x 4 chunks(16B), B 256 rows x 4 chunks
    auto load_stage = [&](int kt, int s) {
        const int kb = kt * BK;                          // in halfs
        const uint32_t ab = sbase + (uint32_t)(s * STAGE_WORDS) * 4;
        const uint32_t bb = ab + A_WORDS * 4;
        #pragma unroll
        for (int t = 0; t < 2; t++) {                    // A: 512 chunks
            int idx = tid + t * 256;
            int r = idx >> 2, c4 = idx & 3;
            int gr = brow + r;
            uint32_t dst = ab + r * 64 + ((c4 ^ ((r >> 1) & 3)) << 4);
            cp16(dst, A + (size_t)gr * K + kb + c4 * 8, (gr < M) ? 16 : 0);
        }
        #pragma unroll
        for (int t = 0; t < 4; t++) {                    // B: 1024 chunks
            int idx = tid + t * 256;
            int r = idx >> 2, c4 = idx & 3;
            uint32_t dst = bb + r * 64 + ((c4 ^ ((r >> 1) & 3)) << 4);
            cp16u(dst, Bt + (size_t)(bcol + r) * K + kb + c4 * 8);
        }
    };

    const int nk = K / BK;
    #pragma unroll
    for (int i = 0; i < STAGES - 1; i++) {
        load_stage(i, i);
        asm volatile("cp.async.commit_group;\n");
    }

    const int fA = ((qr >> 1) & 3) << 2;     // swizzle const (same for all rows ≡ qr mod 8)
    const int rowA0 = warp_m * 64 + qr;
    const int rowB0 = warp_n * 64 + qr;

    for (int kt = 0; kt < nk; kt++) {
        asm volatile("cp.async.wait_group %0;\n" :: "n"(STAGES - 2));
        __syncthreads();

        // prefetch stage kt+STAGES-1 (into the stage freed at kt-1)
        if (kt + STAGES - 1 < nk) load_stage(kt + STAGES - 1, (kt + STAGES - 1) % STAGES);
        asm volatile("cp.async.commit_group;\n");

        const int s = kt % STAGES;
        const uint32_t* As = smem + s * STAGE_WORDS;
        const uint32_t* Bs = As + A_WORDS;

        #pragma unroll
        for (int ks = 0; ks < 2; ks++) {
            const int w0 = ((ks * 8 + qc)     ) ^ fA;
            const int w1 = ((ks * 8 + qc + 4) ) ^ fA;
            uint32_t a[4][4], b[8][2];
            #pragma unroll
            for (int mt = 0; mt < 4; mt++) {
                int r0 = (rowA0 + mt * 16) * 16;
                a[mt][0] = As[r0       + w0];
                a[mt][1] = As[r0 + 128 + w0];      // +8 rows * 16 words
                a[mt][2] = As[r0       + w1];
                a[mt][3] = As[r0 + 128 + w1];
            }
            #pragma unroll
            for (int nt = 0; nt < 8; nt++) {
                int r0 = (rowB0 + nt * 8) * 16;
                b[nt][0] = Bs[r0 + w0];
                b[nt][1] = Bs[r0 + w1];
            }
            #pragma unroll
            for (int mt = 0; mt < 4; mt++)
                #pragma unroll
                for (int nt = 0; nt < 8; nt++)
                    hmma(acc[mt][nt], a[mt], b[nt]);
        }
        __syncthreads();
    }

    // epilogue: f32 pairs
    #pragma unroll
    for (int mt = 0; mt < 4; mt++) {
        int r = brow + warp_m * 64 + mt * 16 + qr;
        #pragma unroll
        for (int nt = 0; nt < 8; nt++) {
            int c = bcol + warp_n * 64 + nt * 8 + qc * 2;
            if (r < M)
                *(float2*)(C + (size_t)r * N + c) =
                    make_float2(acc[mt][nt][0], acc[mt][nt][1]);
            if (r + 8 < M)
                *(float2*)(C + (size_t)(r + 8) * N + c) =
                    make_float2(acc[mt][nt][2], acc[mt][nt][3]);
        }
    }
}

// ---------------------------------------------------------------------------
// f32 -> f16 convert (grid-stride, float4 -> 8B)
// ---------------------------------------------------------------------------
__global__ void to_half(const float4* __restrict__ in, uint2* __restrict__ out, int n4) {
    int i = blockIdx.x * blockDim.x + threadIdx.x;
    int stride = gridDim.x * blockDim.x;
    for (; i < n4; i += stride) {
        float4 v = in[i];
        __half2 h0 = __floats2half2_rn(v.x, v.y);
        __half2 h1 = __floats2half2_rn(v.z, v.w);
        out[i] = make_uint2(*(uint32_t*)&h0, *(uint32_t*)&h1);
    }
}

// ---------------------------------------------------------------------------
// transpose f32 -> f16: out[C][R] = (half)in[R][C]
// ---------------------------------------------------------------------------
__global__ __launch_bounds__(256)
void transpose_h(const float* __restrict__ in, __half* __restrict__ out, int R, int Cc) {
    __shared__ float t[32][33];
    const int c0 = blockIdx.x * 32, r0 = blockIdx.y * 32;
    const int tx = threadIdx.x, ty = threadIdx.y;
    #pragma unroll
    for (int i = ty; i < 32; i += 8)
        t[i][tx] = in[(size_t)(r0 + i) * Cc + c0 + tx];
    __syncthreads();
    #pragma unroll
    for (int i = ty; i < 32; i += 8)
        out[(size_t)(c0 + i) * R + r0 + tx] = __float2half(t[tx][i]);
}

// ---------------------------------------------------------------------------
// Scatter-add: out[dst] += S[src] * w   via vector RED atomics
// ---------------------------------------------------------------------------
template<int D>
__global__ __launch_bounds__(256)
void scatter_add(const float* __restrict__ S, const int* __restrict__ ei,
                 const float* __restrict__ ew, float* __restrict__ out) {
    constexpr int TPE = D / 4;
    constexpr int EPB = 256 / TPE;
    const int e = blockIdx.x * EPB + threadIdx.x / TPE;
    if (e >= N_EDGES) return;
    const int j = threadIdx.x % TPE;
    const int src = ei[e];
    const int dst = ei[N_EDGES + e];
    const float w = ew[e];
    float4 v = ((const float4*)(S + (size_t)src * D))[j];
    v.x *= w; v.y *= w; v.z *= w; v.w *= w;
    float* op = out + (size_t)dst * D + j * 4;
    asm volatile("red.global.add.v4.f32 [%0], {%1,%2,%3,%4};"
                 :: "l"(op), "f"(v.x), "f"(v.y), "f"(v.z), "f"(v.w) : "memory");
}

// ---------------------------------------------------------------------------
// bias+relu -> fp16 (feeds GEMM2)
// ---------------------------------------------------------------------------
template<int D>
__global__ void bias_relu_h(const float* __restrict__ p, const float* __restrict__ b,
                            uint2* __restrict__ out, int n4) {
    int i = blockIdx.x * blockDim.x + threadIdx.x;
    int stride = gridDim.x * blockDim.x;
    for (; i < n4; i += stride) {
        float4 v = ((const float4*)p)[i];
        float4 bb = ((const float4*)b)[i % (D / 4)];
        v.x = fmaxf(v.x + bb.x, 0.f);
        v.y = fmaxf(v.y + bb.y, 0.f);
        v.z = fmaxf(v.z + bb.z, 0.f);
        v.w = fmaxf(v.w + bb.w, 0.f);
        __half2 h0 = __floats2half2_rn(v.x, v.y);
        __half2 h1 = __floats2half2_rn(v.z, v.w);
        out[i] = make_uint2(*(uint32_t*)&h0, *(uint32_t*)&h1);
    }
}

// bias+relu in-place f32 (final output)
template<int D>
__global__ void bias_relu(float* __restrict__ p, const float* __restrict__ b, int n4) {
    int i = blockIdx.x * blockDim.x + threadIdx.x;
    int stride = gridDim.x * blockDim.x;
    for (; i < n4; i += stride) {
        float4 v = ((float4*)p)[i];
        float4 bb = ((const float4*)b)[i % (D / 4)];
        v.x = fmaxf(v.x + bb.x, 0.f);
        v.y = fmaxf(v.y + bb.y, 0.f);
        v.z = fmaxf(v.z + bb.z, 0.f);
        v.w = fmaxf(v.w + bb.w, 0.f);
        ((float4*)p)[i] = v;
    }
}

// ---------------------------------------------------------------------------
// launch
// ---------------------------------------------------------------------------
extern "C" void kernel_launch(void* const* d_in, const int* in_sizes, int n_in,
                              void* d_out, int out_size) {
    const float* x  = (const float*)d_in[0];
    const int*   ei = (const int*)  d_in[1];
    const float* ew = (const float*)d_in[2];
    const float* W1 = (const float*)d_in[3];
    const float* b1 = (const float*)d_in[4];
    const float* W2 = (const float*)d_in[5];
    const float* b2 = (const float*)d_in[6];
    float* out = (float*)d_out;

    float *s1, *h, *s2;
    __half *xh, *hh, *w1t, *w2t;
    cudaGetSymbolAddress((void**)&s1,  g_s1);
    cudaGetSymbolAddress((void**)&h,   g_h);
    cudaGetSymbolAddress((void**)&s2,  g_s2);
    cudaGetSymbolAddress((void**)&xh,  g_xh);
    cudaGetSymbolAddress((void**)&hh,  g_hh);
    cudaGetSymbolAddress((void**)&w1t, g_w1t);
    cudaGetSymbolAddress((void**)&w2t, g_w2t);

    static bool attr_set = false;
    if (!attr_set) {
        cudaFuncSetAttribute(gemm_h, cudaFuncAttributeMaxDynamicSharedMemorySize,
                             SMEM_BYTES);
        attr_set = true;
    }

    const int mblocks = (N_NODES + BM - 1) / BM;   // 391

    // fp16 staging
    to_half<<<4096, 256>>>((const float4*)x, (uint2*)xh, N_NODES * D_IN / 4);
    transpose_h<<<dim3(D_HID / 32, D_IN / 32), dim3(32, 8)>>>(W1, w1t, D_IN, D_HID);
    transpose_h<<<dim3(D_LAT / 32, D_HID / 32), dim3(32, 8)>>>(W2, w2t, D_HID, D_LAT);

    // Layer 1: s1 = x @ W1 ; h = scatter(s1) ; hh = relu(h + b1) fp16
    gemm_h<<<dim3(mblocks, D_HID / BN), 256, SMEM_BYTES>>>(xh, w1t, s1,
                                                           N_NODES, D_HID, D_IN);
    cudaMemsetAsync(h, 0, (size_t)N_NODES * D_HID * sizeof(float));
    scatter_add<D_HID><<<N_EDGES / (256 / (D_HID / 4)), 256>>>(s1, ei, ew, h);
    bias_relu_h<D_HID><<<4096, 256>>>(h, b1, (uint2*)hh, N_NODES * D_HID / 4);

    // Layer 2: s2 = hh @ W2 ; out = relu(scatter(s2) + b2)
    gemm_h<<<dim3(mblocks, D_LAT / BN), 256, SMEM_BYTES>>>(hh, w2t, s2,
                                                           N_NODES, D_LAT, D_HID);
    cudaMemsetAsync(out, 0, (size_t)N_NODES * D_LAT * sizeof(float));
    scatter_add<D_LAT><<<N_EDGES / (256 / (D_LAT / 4)), 256>>>(s2, ei, ew, out);
    bias_relu<D_LAT><<<4096, 256>>>(out, b2, N_NODES * D_LAT / 4);
}